// round 8
// baseline (speedup 1.0000x reference)
#include <cuda_runtime.h>
#include <math.h>
#include <stdint.h>

#define KK 4
#define BB 64
#define SS 50
#define DD 256
#define VV 40000
#define HH 4
#define DHD 64
#define BS (BB*SS)          // 3200
#define BSD (BS*DD)         // 819200
#define FFD (4*DD)          // 1024
#define NEGV (-1e9f)
#define SCL 0.125f          // 1/sqrt(64)

// -------------------- scratch (device globals, no allocation) ----------------
__device__ __align__(16) float g_hloc[KK*BSD];
__device__ __align__(16) float g_h[KK*BSD];      // h_keys accumulators
__device__ __align__(16) float g_x[KK*BSD];
__device__ __align__(16) float g_q[KK*BSD];
__device__ __align__(16) float g_k[KK*BSD];
__device__ __align__(16) float g_v[KK*BSD];
__device__ __align__(16) float g_o[KK*BSD];
__device__ __align__(16) float g_ff[(size_t)KK*BS*FFD];
__device__ __align__(16) float g_hseq[BSD];

__device__ __forceinline__ float warp_sum(float v) {
    #pragma unroll
    for (int o = 16; o; o >>= 1) v += __shfl_xor_sync(0xffffffffu, v, o);
    return v;
}
__device__ __forceinline__ float warp_max(float v) {
    #pragma unroll
    for (int o = 16; o; o >>= 1) v = fmaxf(v, __shfl_xor_sync(0xffffffffu, v, o));
    return v;
}
__device__ __forceinline__ float gelu_f(float x) {
    float x3 = x * x * x;
    return 0.5f * x * (1.0f + tanhf(0.7978845608028654f * (x + 0.044715f * x3)));
}
__device__ __forceinline__ uint32_t f2tf(float x) {
    uint32_t r; asm("cvt.rna.tf32.f32 %0, %1;" : "=r"(r) : "f"(x)); return r;
}
__device__ __forceinline__ void mma_tf32(float d[4],
                                         uint32_t a0, uint32_t a1, uint32_t a2, uint32_t a3,
                                         uint32_t b0, uint32_t b1) {
    asm volatile(
        "mma.sync.aligned.m16n8k8.row.col.f32.tf32.tf32.f32 "
        "{%0,%1,%2,%3}, {%4,%5,%6,%7}, {%8,%9}, {%0,%1,%2,%3};"
        : "+f"(d[0]), "+f"(d[1]), "+f"(d[2]), "+f"(d[3])
        : "r"(a0), "r"(a1), "r"(a2), "r"(a3), "r"(b0), "r"(b1));
}

// -------------------- local aggregator, fused emb-gather, batched over k -----
// grid (BB, KK); dyn smem: hg[50*256] | a[4*256] | alpha[50*50]
__global__ void localagg_kernel(const float* __restrict__ emb,
                                const int* __restrict__ items,
                                const int* __restrict__ adj,
                                const float* __restrict__ agg_a,
                                float* __restrict__ hloc) {
    extern __shared__ float sm[];
    float* sm_hg = sm;               // 12800 floats
    float* sm_a  = sm + 12800;       // 1024
    float* sm_al = sm + 13824;       // 2500
    int b = blockIdx.x;
    int key = blockIdx.y;
    int tid = threadIdx.x;
    const float* emb_k = emb + (size_t)key * VV * DD;
    const int* items_k = items + (size_t)key * BS + (size_t)b * SS;
    // fused gather: hg = emb[items]
    for (int t = tid; t < SS * DD; t += 256) {
        int s = t >> 8, d = t & 255;
        int it = items_k[s];
        sm_hg[t] = emb_k[(size_t)it * DD + d];
    }
    for (int t = tid; t < 4 * DD; t += 256)
        sm_a[t] = agg_a[(size_t)key * 4 * DD + t];
    __syncthreads();

    int w = tid >> 5, lane = tid & 31;
    // relation-typed scores for present edges (float4 vectorized)
    for (int p = w; p < SS * SS; p += 8) {
        int i = p / SS, j = p % SS;
        int r = adj[(size_t)b * SS * SS + p];
        float val = NEGV;
        if (r != 0) {
            const float4* hi4 = (const float4*)(sm_hg + i * DD);
            const float4* hj4 = (const float4*)(sm_hg + j * DD);
            const float4* ar4 = (const float4*)(sm_a + (r - 1) * DD);
            float acc = 0.0f;
            #pragma unroll
            for (int t = 0; t < 2; t++) {
                int idx = lane + t * 32;
                float4 a = hi4[idx], bb = hj4[idx], c = ar4[idx];
                acc = fmaf(a.x * bb.x, c.x, acc);
                acc = fmaf(a.y * bb.y, c.y, acc);
                acc = fmaf(a.z * bb.z, c.z, acc);
                acc = fmaf(a.w * bb.w, c.w, acc);
            }
            acc = warp_sum(acc);
            val = (acc >= 0.0f) ? acc : 0.2f * acc;   // leaky_relu 0.2
        }
        if (lane == 0) sm_al[p] = val;
    }
    __syncthreads();
    // row softmax (all-NEG rows -> uniform, matching jax)
    for (int i = w; i < SS; i += 8) {
        float v0 = (lane < SS) ? sm_al[i * SS + lane] : -INFINITY;
        float v1 = (lane + 32 < SS) ? sm_al[i * SS + lane + 32] : -INFINITY;
        float m = warp_max(fmaxf(v0, v1));
        float e0 = (lane < SS) ? expf(v0 - m) : 0.0f;
        float e1 = (lane + 32 < SS) ? expf(v1 - m) : 0.0f;
        float s = warp_sum(e0 + e1);
        float inv = 1.0f / s;
        if (lane < SS) sm_al[i * SS + lane] = e0 * inv;
        if (lane + 32 < SS) sm_al[i * SS + lane + 32] = e1 * inv;
    }
    __syncthreads();
    // h_local = alpha @ hg
    float* outp = hloc + (size_t)key * BSD + (size_t)b * SS * DD;
    for (int idx = tid; idx < SS * DD; idx += 256) {
        int i = idx >> 8, d = idx & 255;
        float acc = 0.0f;
        #pragma unroll 10
        for (int j = 0; j < SS; j++) acc += sm_al[i * SS + j] * sm_hg[j * DD + d];
        outp[idx] = acc;
    }
}

// -------------------- batched LayerNorm (optional alias-gather + copy) -------
// grid (BS, KK), 256 threads
__global__ void ln_bat_kernel(const float* __restrict__ in,
                              const int* __restrict__ alias,   // may be null
                              const float* __restrict__ g,
                              const float* __restrict__ bta,
                              float* __restrict__ copy_out,     // may be null
                              float* __restrict__ x) {
    int key = blockIdx.y, bs = blockIdx.x, d = threadIdx.x;
    size_t src;
    if (alias) {
        int b = bs / SS;
        src = (size_t)key * BSD + ((size_t)b * SS + alias[bs]) * DD + d;
    } else {
        src = (size_t)key * BSD + (size_t)bs * DD + d;
    }
    float v = in[src];
    size_t dst = (size_t)key * BSD + (size_t)bs * DD + d;
    if (copy_out) copy_out[dst] = v;
    __shared__ float sm[8], sv[8];
    int w = d >> 5, lane = d & 31;
    float s = warp_sum(v), q = warp_sum(v * v);
    if (lane == 0) { sm[w] = s; sv[w] = q; }
    __syncthreads();
    float tm = 0.0f, tv = 0.0f;
    #pragma unroll
    for (int j = 0; j < 8; j++) { tm += sm[j]; tv += sv[j]; }
    float mean = tm * (1.0f / DD);
    float var = fmaxf(tv * (1.0f / DD) - mean * mean, 0.0f);
    float inv = rsqrtf(var + 1e-5f);
    x[dst] = (v - mean) * inv * g[key * DD + d] + bta[key * DD + d];
}

// -------------------- 128x128x8 tensor-core GEMM (3xTF32, fp32 accuracy) -----
// C[M,N] = act(A[M,K] @ B[K,N] + Res)  ;  M%128==0, N%128==0, K%8==0
#define TBM 128
#define TBN 128
#define TBK 8
#define ASTR (TBM + 4)      // padded stride -> conflict-free fragment loads
#define BSTR (TBN + 4)
__device__ __forceinline__ void gemm_tile_tf32(const float* __restrict__ A,
                                               const float* __restrict__ Bm,
                                               const float* __restrict__ Res,
                                               float* __restrict__ C,
                                               int N, int Kd, int act) {
    __shared__ uint32_t Ah[2][TBK][ASTR];
    __shared__ uint32_t Al[2][TBK][ASTR];
    __shared__ uint32_t Bh[2][TBK][BSTR];
    __shared__ uint32_t Bl[2][TBK][BSTR];

    int tid = threadIdx.x;
    int wid = tid >> 5, lane = tid & 31;
    int wm = wid & 1, wn = wid >> 1;          // warp tile 64(m) x 32(n)
    int lk = lane & 3, lm = lane >> 2;
    int row0 = blockIdx.y * TBM, col0 = blockIdx.x * TBN;
    int aRow = tid >> 1, aCol = (tid & 1) * 4;   // A: 128 rows x 8 k, float4/thread
    int bRow = tid >> 5, bCol = (tid & 31) * 4;  // B: 8 k x 128 cols, float4/thread
    const float* Aptr = A + (size_t)(row0 + aRow) * Kd + aCol;
    const float* Bptr = Bm + (size_t)bRow * N + col0 + bCol;

    float4 a_ld = *(const float4*)Aptr;
    float4 b_ld = *(const float4*)Bptr;
    {
        float av[4] = {a_ld.x, a_ld.y, a_ld.z, a_ld.w};
        float bv[4] = {b_ld.x, b_ld.y, b_ld.z, b_ld.w};
        uint32_t bh[4], bl[4];
        #pragma unroll
        for (int i = 0; i < 4; i++) {
            uint32_t h = f2tf(av[i]);
            Ah[0][aCol + i][aRow] = h;
            Al[0][aCol + i][aRow] = f2tf(av[i] - __uint_as_float(h));
            bh[i] = f2tf(bv[i]);
            bl[i] = f2tf(bv[i] - __uint_as_float(bh[i]));
        }
        *(uint4*)&Bh[0][bRow][bCol] = make_uint4(bh[0], bh[1], bh[2], bh[3]);
        *(uint4*)&Bl[0][bRow][bCol] = make_uint4(bl[0], bl[1], bl[2], bl[3]);
    }
    __syncthreads();

    float acc[4][4][4] = {};   // [mt][nt][frag]
    int buf = 0;
    for (int k0 = TBK; k0 <= Kd; k0 += TBK) {
        bool has = (k0 < Kd);
        if (has) {
            a_ld = *(const float4*)(Aptr + k0);
            b_ld = *(const float4*)(Bptr + (size_t)k0 * N);
        }
        // load A fragments (hi/lo)
        uint32_t ah[4][4], alf[4][4];
        #pragma unroll
        for (int mt = 0; mt < 4; mt++) {
            int mr = wm * 64 + mt * 16 + lm;
            ah[mt][0]  = Ah[buf][lk][mr];      alf[mt][0] = Al[buf][lk][mr];
            ah[mt][1]  = Ah[buf][lk][mr + 8];  alf[mt][1] = Al[buf][lk][mr + 8];
            ah[mt][2]  = Ah[buf][lk + 4][mr];      alf[mt][2] = Al[buf][lk + 4][mr];
            ah[mt][3]  = Ah[buf][lk + 4][mr + 8];  alf[mt][3] = Al[buf][lk + 4][mr + 8];
        }
        #pragma unroll
        for (int nt = 0; nt < 4; nt++) {
            int nc = wn * 32 + nt * 8 + lm;
            uint32_t bh0 = Bh[buf][lk][nc], bh1 = Bh[buf][lk + 4][nc];
            uint32_t bl0 = Bl[buf][lk][nc], bl1 = Bl[buf][lk + 4][nc];
            #pragma unroll
            for (int mt = 0; mt < 4; mt++) {
                mma_tf32(acc[mt][nt], alf[mt][0], alf[mt][1], alf[mt][2], alf[mt][3], bh0, bh1);
                mma_tf32(acc[mt][nt], ah[mt][0],  ah[mt][1],  ah[mt][2],  ah[mt][3],  bl0, bl1);
                mma_tf32(acc[mt][nt], ah[mt][0],  ah[mt][1],  ah[mt][2],  ah[mt][3],  bh0, bh1);
            }
        }
        if (has) {
            int nb = buf ^ 1;
            float av[4] = {a_ld.x, a_ld.y, a_ld.z, a_ld.w};
            float bv[4] = {b_ld.x, b_ld.y, b_ld.z, b_ld.w};
            uint32_t bh[4], bl[4];
            #pragma unroll
            for (int i = 0; i < 4; i++) {
                uint32_t h = f2tf(av[i]);
                Ah[nb][aCol + i][aRow] = h;
                Al[nb][aCol + i][aRow] = f2tf(av[i] - __uint_as_float(h));
                bh[i] = f2tf(bv[i]);
                bl[i] = f2tf(bv[i] - __uint_as_float(bh[i]));
            }
            *(uint4*)&Bh[nb][bRow][bCol] = make_uint4(bh[0], bh[1], bh[2], bh[3]);
            *(uint4*)&Bl[nb][bRow][bCol] = make_uint4(bl[0], bl[1], bl[2], bl[3]);
            __syncthreads();
            buf = nb;
        }
    }
    // epilogue: C-fragment c0,c1 -> (row, col 2lk..2lk+1); c2,c3 -> row+8
    #pragma unroll
    for (int mt = 0; mt < 4; mt++) {
        #pragma unroll
        for (int half = 0; half < 2; half++) {
            int r = row0 + wm * 64 + mt * 16 + lm + half * 8;
            #pragma unroll
            for (int nt = 0; nt < 4; nt++) {
                float v0 = acc[mt][nt][half * 2 + 0];
                float v1 = acc[mt][nt][half * 2 + 1];
                size_t off = (size_t)r * N + col0 + wn * 32 + nt * 8 + 2 * lk;
                if (Res) {
                    float2 rv = *(const float2*)(Res + off);
                    v0 += rv.x; v1 += rv.y;
                }
                if (act == 1) { v0 = gelu_f(v0); v1 = gelu_f(v1); }
                *(float2*)(C + off) = make_float2(v0, v1);
            }
        }
    }
}

// batched generic: blockIdx.z selects slice via element strides
__global__ void __launch_bounds__(256)
gemm_bat_kernel(const float* __restrict__ A, size_t sA,
                const float* __restrict__ Bm, size_t sB,
                const float* __restrict__ Res, size_t sR,
                float* __restrict__ C, size_t sC,
                int N, int Kd, int act) {
    size_t z = blockIdx.z;
    gemm_tile_tf32(A + z * sA, Bm + z * sB,
                   Res ? Res + z * sR : nullptr, C + z * sC, N, Kd, act);
}

// QKV fused-batched: blockIdx.z = key*3 + {0:Q,1:K,2:V}
__global__ void __launch_bounds__(256)
gemm_qkv_kernel(const float* __restrict__ x,
                const float* __restrict__ Wq,
                const float* __restrict__ Wk,
                const float* __restrict__ Wv,
                float* __restrict__ q,
                float* __restrict__ k,
                float* __restrict__ v) {
    int z = blockIdx.z;
    int key = z / 3, m = z - key * 3;
    const float* A = x + (size_t)key * BSD;
    const float* B = (m == 0 ? Wq : m == 1 ? Wk : Wv) + (size_t)key * DD * DD;
    float* C = (m == 0 ? q : m == 1 ? k : v) + (size_t)key * BSD;
    gemm_tile_tf32(A, B, nullptr, C, DD, DD, 0);
}

// -------------------- causal MHA, batched over k: grid (BB, HH, KK) ----------
__global__ void attn_kernel(const float* __restrict__ q,
                            const float* __restrict__ k,
                            const float* __restrict__ v,
                            float* __restrict__ o) {
    __shared__ float sq[SS * (DHD + 1)];
    __shared__ float sk[SS * (DHD + 1)];
    __shared__ float sv[SS * (DHD + 1)];
    __shared__ float sp[8 * 64];
    int b = blockIdx.x, h = blockIdx.y;
    size_t kb = (size_t)blockIdx.z * BSD;
    for (int t = threadIdx.x; t < SS * DHD; t += 256) {
        int s = t / DHD, d = t % DHD;
        size_t gi = kb + ((size_t)b * SS + s) * DD + h * DHD + d;
        int si = s * (DHD + 1) + d;
        sq[si] = q[gi]; sk[si] = k[gi]; sv[si] = v[gi];
    }
    __syncthreads();
    int w = threadIdx.x >> 5, lane = threadIdx.x & 31;
    for (int i = w; i < SS; i += 8) {
        float sc[2];
        #pragma unroll
        for (int jj = 0; jj < 2; jj++) {
            int j = lane + jj * 32;
            float val = NEGV;
            if (j < SS && j <= i) {
                float acc = 0.0f;
                #pragma unroll 16
                for (int d = 0; d < DHD; d++)
                    acc += sq[i * (DHD + 1) + d] * sk[j * (DHD + 1) + d];
                val = acc * SCL;
            }
            sc[jj] = val;
        }
        float m = warp_max(fmaxf(sc[0], sc[1]));
        float e0 = expf(sc[0] - m), e1 = expf(sc[1] - m);
        if (lane + 32 >= SS) e1 = 0.0f;
        float s = warp_sum(e0 + e1);
        float inv = 1.0f / s;
        sp[w * 64 + lane] = e0 * inv;
        if (lane + 32 < 64) sp[w * 64 + 32 + lane] = e1 * inv;
        __syncwarp();
        #pragma unroll
        for (int dd = 0; dd < 2; dd++) {
            int d = lane + dd * 32;
            float acc = 0.0f;
            #pragma unroll 10
            for (int j = 0; j < SS; j++)
                acc += sp[w * 64 + j] * sv[j * (DHD + 1) + d];
            o[kb + ((size_t)b * SS + i) * DD + h * DHD + d] = acc;
        }
    }
}

// -------------------- h_seq = mean_k emb[k][ids[k]] --------------------------
__global__ void hseq_kernel(const float* __restrict__ emb,
                            const int* __restrict__ ids,
                            float* __restrict__ hseq) {
    int bs = blockIdx.x, d = threadIdx.x;
    float acc = 0.0f;
    #pragma unroll
    for (int kk = 0; kk < KK; kk++) {
        int id = ids[(size_t)kk * BS + bs];
        acc += emb[(size_t)kk * VV * DD + (size_t)id * DD + d];
    }
    hseq[(size_t)bs * DD + d] = acc * 0.25f;
}

// -------------------- noisy top-2 gating + combine ---------------------------
__global__ void gate_kernel(const float* __restrict__ hseq,
                            const float* __restrict__ Wg,
                            const float* __restrict__ Wn,
                            const float* __restrict__ eps,
                            const float* __restrict__ hk,
                            float* __restrict__ out) {
    __shared__ float red[8 * 256];
    __shared__ float sg[KK];
    int bs = blockIdx.x, d = threadIdx.x;
    float hx = hseq[(size_t)bs * DD + d];
    #pragma unroll
    for (int kk = 0; kk < KK; kk++) {
        red[kk * 256 + d]       = hx * Wg[d * KK + kk];
        red[(4 + kk) * 256 + d] = hx * Wn[d * KK + kk];
    }
    __syncthreads();
    for (int st = 128; st > 0; st >>= 1) {
        if (d < st) {
            #pragma unroll
            for (int j = 0; j < 8; j++)
                red[j * 256 + d] += red[j * 256 + d + st];
        }
        __syncthreads();
    }
    if (d == 0) {
        float lg[KK];
        #pragma unroll
        for (int kk = 0; kk < KK; kk++) {
            float noise = red[(4 + kk) * 256];
            float sp = (noise > 0.0f) ? (noise + log1pf(expf(-noise)))
                                      : log1pf(expf(noise));
            lg[kk] = red[kk * 256] + sp * eps[(size_t)bs * KK + kk];
        }
        int i1 = 0; float v1 = lg[0];
        #pragma unroll
        for (int kk = 1; kk < KK; kk++) if (lg[kk] > v1) { v1 = lg[kk]; i1 = kk; }
        int i2 = -1; float v2 = -INFINITY;
        #pragma unroll
        for (int kk = 0; kk < KK; kk++)
            if (kk != i1 && lg[kk] > v2) { v2 = lg[kk]; i2 = kk; }
        float e2 = expf(v2 - v1);
        float den = 1.0f / (1.0f + e2);
        #pragma unroll
        for (int kk = 0; kk < KK; kk++) sg[kk] = 0.0f;
        sg[i1] = den;
        sg[i2] = e2 * den;
    }
    __syncthreads();
    float acc = 0.0f;
    #pragma unroll
    for (int kk = 0; kk < KK; kk++)
        acc += sg[kk] * hk[(size_t)kk * BSD + (size_t)bs * DD + d];
    out[(size_t)bs * DD + d] = acc;
}

// -------------------- launch -------------------------------------------------
extern "C" void kernel_launch(void* const* d_in, const int* in_sizes, int n_in,
                              void* d_out, int out_size) {
    const int*   ids   = (const int*)d_in[0];
    const int*   items = (const int*)d_in[1];
    const int*   adj   = (const int*)d_in[2];
    const int*   alias = (const int*)d_in[3];
    const float* eps   = (const float*)d_in[4];
    const float* emb   = (const float*)d_in[5];
    const float* agg_a = (const float*)d_in[6];
    const float* Wq    = (const float*)d_in[7];
    const float* Wk    = (const float*)d_in[8];
    const float* Wv    = (const float*)d_in[9];
    const float* Wo    = (const float*)d_in[10];
    const float* ln1g  = (const float*)d_in[11];
    const float* ln1b  = (const float*)d_in[12];
    const float* W1    = (const float*)d_in[13];
    const float* W2    = (const float*)d_in[14];
    const float* ln2g  = (const float*)d_in[15];
    const float* ln2b  = (const float*)d_in[16];
    const float* Wg    = (const float*)d_in[17];
    const float* Wn    = (const float*)d_in[18];
    float* out = (float*)d_out;

    float *p_hloc, *p_h, *p_x, *p_q, *p_k, *p_v, *p_o, *p_ff, *p_hseq;
    cudaGetSymbolAddress((void**)&p_hloc, g_hloc);
    cudaGetSymbolAddress((void**)&p_h,    g_h);
    cudaGetSymbolAddress((void**)&p_x,    g_x);
    cudaGetSymbolAddress((void**)&p_q,    g_q);
    cudaGetSymbolAddress((void**)&p_k,    g_k);
    cudaGetSymbolAddress((void**)&p_v,    g_v);
    cudaGetSymbolAddress((void**)&p_o,    g_o);
    cudaGetSymbolAddress((void**)&p_ff,   g_ff);
    cudaGetSymbolAddress((void**)&p_hseq, g_hseq);

    const int smem_agg = (SS * DD + 4 * DD + SS * SS) * sizeof(float);  // 65296
    cudaFuncSetAttribute(localagg_kernel,
                         cudaFuncAttributeMaxDynamicSharedMemorySize, smem_agg);

    const size_t sW = (size_t)DD * DD;
    const size_t sFF = (size_t)BS * FFD;

    hseq_kernel<<<BS, 256>>>(emb, ids, p_hseq);

    // graph aggregation + alias + LN1, all keys at once
    localagg_kernel<<<dim3(BB, KK), 256, smem_agg>>>(emb, items, adj, agg_a, p_hloc);
    ln_bat_kernel<<<dim3(BS, KK), 256>>>(p_hloc, alias, ln1g, ln1b, p_h, p_x);

    // QKV for all keys (12 GEMMs in one launch)
    gemm_qkv_kernel<<<dim3(DD / TBN, BS / TBM, KK * 3), 256>>>(
        p_x, Wq, Wk, Wv, p_q, p_k, p_v);

    attn_kernel<<<dim3(BB, HH, KK), 256>>>(p_q, p_k, p_v, p_o);

    // h += O @ Wo   (all keys)
    gemm_bat_kernel<<<dim3(DD / TBN, BS / TBM, KK), 256>>>(
        p_o, (size_t)BSD, Wo, sW, p_h, (size_t)BSD, p_h, (size_t)BSD, DD, DD, 0);

    // LN2 (all keys)
    ln_bat_kernel<<<dim3(BS, KK), 256>>>(p_h, nullptr, ln2g, ln2b, nullptr, p_x);

    // FFN1: gelu(x @ W1)  (all keys)
    gemm_bat_kernel<<<dim3(FFD / TBN, BS / TBM, KK), 256>>>(
        p_x, (size_t)BSD, W1, (size_t)DD * FFD, nullptr, 0, p_ff, sFF, FFD, DD, 1);

    // FFN2: h += ff @ W2  (all keys)
    gemm_bat_kernel<<<dim3(DD / TBN, BS / TBM, KK), 256>>>(
        p_ff, sFF, W2, (size_t)FFD * DD, p_h, (size_t)BSD, p_h, (size_t)BSD, DD, FFD, 0);

    gate_kernel<<<BS, 256>>>(p_hseq, Wg, Wn, eps, p_h, out);
}

// round 9
// speedup vs baseline: 1.3872x; 1.3872x over previous
#include <cuda_runtime.h>
#include <cuda_bf16.h>
#include <math.h>
#include <stdint.h>

#define KK 4
#define BB 64
#define SS 50
#define DD 256
#define VV 40000
#define HH 4
#define DHD 64
#define BS (BB*SS)          // 3200
#define BSD (BS*DD)         // 819200
#define FFD (4*DD)          // 1024
#define NEGV (-1e9f)
#define SCL 0.125f          // 1/sqrt(64)

// -------------------- scratch (device globals, no allocation) ----------------
__device__ __align__(16) float g_hloc[KK*BSD];
__device__ __align__(16) float g_h[KK*BSD];      // h_keys accumulators
__device__ __align__(16) float g_x[KK*BSD];
__device__ __align__(16) float g_q[KK*BSD];
__device__ __align__(16) float g_k[KK*BSD];
__device__ __align__(16) float g_v[KK*BSD];
__device__ __align__(16) float g_o[KK*BSD];
__device__ __align__(16) float g_ff[(size_t)KK*BS*FFD];
__device__ __align__(16) float g_hseq[BSD];

__device__ __forceinline__ float warp_sum(float v) {
    #pragma unroll
    for (int o = 16; o; o >>= 1) v += __shfl_xor_sync(0xffffffffu, v, o);
    return v;
}
__device__ __forceinline__ float warp_max(float v) {
    #pragma unroll
    for (int o = 16; o; o >>= 1) v = fmaxf(v, __shfl_xor_sync(0xffffffffu, v, o));
    return v;
}
__device__ __forceinline__ float gelu_f(float x) {
    float x3 = x * x * x;
    return 0.5f * x * (1.0f + tanhf(0.7978845608028654f * (x + 0.044715f * x3)));
}
// pack two bf16 (lo -> low half, hi -> high half)
__device__ __forceinline__ uint32_t packb(__nv_bfloat16 lo, __nv_bfloat16 hi) {
    __nv_bfloat162 t = __halves2bfloat162(lo, hi);
    return *(uint32_t*)&t;
}
// split x into bf16 hi + residual lo (bf16)
__device__ __forceinline__ void split_bf16(float x, __nv_bfloat16& h, __nv_bfloat16& l) {
    h = __float2bfloat16(x);
    l = __float2bfloat16(x - __bfloat162float(h));
}
__device__ __forceinline__ void mma_bf16(float d[4],
                                         uint32_t a0, uint32_t a1, uint32_t a2, uint32_t a3,
                                         uint32_t b0, uint32_t b1) {
    asm volatile(
        "mma.sync.aligned.m16n8k16.row.col.f32.bf16.bf16.f32 "
        "{%0,%1,%2,%3}, {%4,%5,%6,%7}, {%8,%9}, {%0,%1,%2,%3};"
        : "+f"(d[0]), "+f"(d[1]), "+f"(d[2]), "+f"(d[3])
        : "r"(a0), "r"(a1), "r"(a2), "r"(a3), "r"(b0), "r"(b1));
}

// -------------------- local aggregator, fused emb-gather, batched over k -----
// grid (BB, KK); dyn smem: hg[50*256] | a[4*256] | alpha[50*50]
__global__ void localagg_kernel(const float* __restrict__ emb,
                                const int* __restrict__ items,
                                const int* __restrict__ adj,
                                const float* __restrict__ agg_a,
                                float* __restrict__ hloc) {
    extern __shared__ float sm[];
    float* sm_hg = sm;               // 12800 floats
    float* sm_a  = sm + 12800;       // 1024
    float* sm_al = sm + 13824;       // 2500
    int b = blockIdx.x;
    int key = blockIdx.y;
    int tid = threadIdx.x;
    const float* emb_k = emb + (size_t)key * VV * DD;
    const int* items_k = items + (size_t)key * BS + (size_t)b * SS;
    // fused gather: hg = emb[items]
    for (int t = tid; t < SS * DD; t += 256) {
        int s = t >> 8, d = t & 255;
        int it = items_k[s];
        sm_hg[t] = emb_k[(size_t)it * DD + d];
    }
    for (int t = tid; t < 4 * DD; t += 256)
        sm_a[t] = agg_a[(size_t)key * 4 * DD + t];
    __syncthreads();

    int w = tid >> 5, lane = tid & 31;
    // relation-typed scores for present edges (float4 vectorized)
    for (int p = w; p < SS * SS; p += 8) {
        int i = p / SS, j = p % SS;
        int r = adj[(size_t)b * SS * SS + p];
        float val = NEGV;
        if (r != 0) {
            const float4* hi4 = (const float4*)(sm_hg + i * DD);
            const float4* hj4 = (const float4*)(sm_hg + j * DD);
            const float4* ar4 = (const float4*)(sm_a + (r - 1) * DD);
            float acc = 0.0f;
            #pragma unroll
            for (int t = 0; t < 2; t++) {
                int idx = lane + t * 32;
                float4 a = hi4[idx], bb = hj4[idx], c = ar4[idx];
                acc = fmaf(a.x * bb.x, c.x, acc);
                acc = fmaf(a.y * bb.y, c.y, acc);
                acc = fmaf(a.z * bb.z, c.z, acc);
                acc = fmaf(a.w * bb.w, c.w, acc);
            }
            acc = warp_sum(acc);
            val = (acc >= 0.0f) ? acc : 0.2f * acc;   // leaky_relu 0.2
        }
        if (lane == 0) sm_al[p] = val;
    }
    __syncthreads();
    // row softmax (all-NEG rows -> uniform, matching jax)
    for (int i = w; i < SS; i += 8) {
        float v0 = (lane < SS) ? sm_al[i * SS + lane] : -INFINITY;
        float v1 = (lane + 32 < SS) ? sm_al[i * SS + lane + 32] : -INFINITY;
        float m = warp_max(fmaxf(v0, v1));
        float e0 = (lane < SS) ? expf(v0 - m) : 0.0f;
        float e1 = (lane + 32 < SS) ? expf(v1 - m) : 0.0f;
        float s = warp_sum(e0 + e1);
        float inv = 1.0f / s;
        if (lane < SS) sm_al[i * SS + lane] = e0 * inv;
        if (lane + 32 < SS) sm_al[i * SS + lane + 32] = e1 * inv;
    }
    __syncthreads();
    // h_local = alpha @ hg
    float* outp = hloc + (size_t)key * BSD + (size_t)b * SS * DD;
    for (int idx = tid; idx < SS * DD; idx += 256) {
        int i = idx >> 8, d = idx & 255;
        float acc = 0.0f;
        #pragma unroll 10
        for (int j = 0; j < SS; j++) acc += sm_al[i * SS + j] * sm_hg[j * DD + d];
        outp[idx] = acc;
    }
}

// -------------------- batched LayerNorm (optional alias-gather + copy) -------
// grid (BS, KK), 256 threads
__global__ void ln_bat_kernel(const float* __restrict__ in,
                              const int* __restrict__ alias,   // may be null
                              const float* __restrict__ g,
                              const float* __restrict__ bta,
                              float* __restrict__ copy_out,     // may be null
                              float* __restrict__ x) {
    int key = blockIdx.y, bs = blockIdx.x, d = threadIdx.x;
    size_t src;
    if (alias) {
        int b = bs / SS;
        src = (size_t)key * BSD + ((size_t)b * SS + alias[bs]) * DD + d;
    } else {
        src = (size_t)key * BSD + (size_t)bs * DD + d;
    }
    float v = in[src];
    size_t dst = (size_t)key * BSD + (size_t)bs * DD + d;
    if (copy_out) copy_out[dst] = v;
    __shared__ float sm[8], sv[8];
    int w = d >> 5, lane = d & 31;
    float s = warp_sum(v), q = warp_sum(v * v);
    if (lane == 0) { sm[w] = s; sv[w] = q; }
    __syncthreads();
    float tm = 0.0f, tv = 0.0f;
    #pragma unroll
    for (int j = 0; j < 8; j++) { tm += sm[j]; tv += sv[j]; }
    float mean = tm * (1.0f / DD);
    float var = fmaxf(tv * (1.0f / DD) - mean * mean, 0.0f);
    float inv = rsqrtf(var + 1e-5f);
    x[dst] = (v - mean) * inv * g[key * DD + d] + bta[key * DD + d];
}

// ------------- 128x128x16 tensor-core GEMM (3xBF16, ~fp32 accuracy) ----------
// C[M,N] = act(A[M,K] @ B[K,N] + Res)  ;  M%128==0, N%128==0, K%16==0
// smem stores bf16x2 pairs along k: [kpair 0..7][row/col], stride 136 (pad 8)
// -> fragment loads conflict-free (bank = (8*lk + lm) % 32, all distinct)
#define TBM 128
#define TBN 128
#define TBK 16
#define ASTR (TBM + 8)
#define BSTR (TBN + 8)
__device__ __forceinline__ void gemm_tile_bf16(const float* __restrict__ A,
                                               const float* __restrict__ Bm,
                                               const float* __restrict__ Res,
                                               float* __restrict__ C,
                                               int N, int Kd, int act) {
    __shared__ uint32_t Ah[2][8][ASTR];
    __shared__ uint32_t Al[2][8][ASTR];
    __shared__ uint32_t Bh[2][8][BSTR];
    __shared__ uint32_t Bl[2][8][BSTR];

    int tid = threadIdx.x;
    int wid = tid >> 5, lane = tid & 31;
    int wm = wid & 1, wn = wid >> 1;          // warp tile 64(m) x 32(n)
    int lk = lane & 3, lm = lane >> 2;
    int row0 = blockIdx.y * TBM, col0 = blockIdx.x * TBN;
    // A loader: 128 rows x 16 k; thread -> row (tid>>1), k block (tid&1)*8
    int aRow = tid >> 1, aK = (tid & 1) * 8;
    // B loader: thread -> kpair (tid>>5), 4 cols (tid&31)*4
    int bKp = tid >> 5, bCol = (tid & 31) * 4;
    const float* Aptr = A + (size_t)(row0 + aRow) * Kd + aK;
    const float* Bptr0 = Bm + (size_t)(2 * bKp) * N + col0 + bCol;
    const float* Bptr1 = Bm + (size_t)(2 * bKp + 1) * N + col0 + bCol;

    float4 aL0 = *(const float4*)Aptr;
    float4 aL1 = *(const float4*)(Aptr + 4);
    float4 bL0 = *(const float4*)Bptr0;
    float4 bL1 = *(const float4*)Bptr1;

    // stage-0 convert + store
    {
        float av[8] = {aL0.x, aL0.y, aL0.z, aL0.w, aL1.x, aL1.y, aL1.z, aL1.w};
        #pragma unroll
        for (int j = 0; j < 4; j++) {
            __nv_bfloat16 h0, l0, h1, l1;
            split_bf16(av[2 * j], h0, l0);
            split_bf16(av[2 * j + 1], h1, l1);
            Ah[0][aK / 2 + j][aRow] = packb(h0, h1);
            Al[0][aK / 2 + j][aRow] = packb(l0, l1);
        }
        float bx[4] = {bL0.x, bL0.y, bL0.z, bL0.w};
        float by[4] = {bL1.x, bL1.y, bL1.z, bL1.w};
        uint32_t bhv[4], blv[4];
        #pragma unroll
        for (int c = 0; c < 4; c++) {
            __nv_bfloat16 h0, l0, h1, l1;
            split_bf16(bx[c], h0, l0);   // k = 2*kp   -> low half
            split_bf16(by[c], h1, l1);   // k = 2*kp+1 -> high half
            bhv[c] = packb(h0, h1);
            blv[c] = packb(l0, l1);
        }
        *(uint4*)&Bh[0][bKp][bCol] = make_uint4(bhv[0], bhv[1], bhv[2], bhv[3]);
        *(uint4*)&Bl[0][bKp][bCol] = make_uint4(blv[0], blv[1], blv[2], blv[3]);
    }
    __syncthreads();

    float acc[4][4][4] = {};   // [mt][nt][frag]
    int buf = 0;
    for (int k0 = TBK; k0 <= Kd; k0 += TBK) {
        bool has = (k0 < Kd);
        if (has) {
            aL0 = *(const float4*)(Aptr + k0);
            aL1 = *(const float4*)(Aptr + k0 + 4);
            bL0 = *(const float4*)(Bptr0 + (size_t)k0 * N);
            bL1 = *(const float4*)(Bptr1 + (size_t)k0 * N);
        }
        // A fragments (hi/lo): a0=(lk,lm) a1=(lk,lm+8) a2=(lk+4,lm) a3=(lk+4,lm+8)
        uint32_t ah[4][4], alf[4][4];
        #pragma unroll
        for (int mt = 0; mt < 4; mt++) {
            int mr = wm * 64 + mt * 16 + lm;
            ah[mt][0] = Ah[buf][lk][mr];       alf[mt][0] = Al[buf][lk][mr];
            ah[mt][1] = Ah[buf][lk][mr + 8];   alf[mt][1] = Al[buf][lk][mr + 8];
            ah[mt][2] = Ah[buf][lk + 4][mr];       alf[mt][2] = Al[buf][lk + 4][mr];
            ah[mt][3] = Ah[buf][lk + 4][mr + 8];   alf[mt][3] = Al[buf][lk + 4][mr + 8];
        }
        #pragma unroll
        for (int nt = 0; nt < 4; nt++) {
            int nc = wn * 32 + nt * 8 + lm;
            uint32_t bh0 = Bh[buf][lk][nc], bh1 = Bh[buf][lk + 4][nc];
            uint32_t bl0 = Bl[buf][lk][nc], bl1 = Bl[buf][lk + 4][nc];
            #pragma unroll
            for (int mt = 0; mt < 4; mt++) {
                mma_bf16(acc[mt][nt], alf[mt][0], alf[mt][1], alf[mt][2], alf[mt][3], bh0, bh1);
                mma_bf16(acc[mt][nt], ah[mt][0],  ah[mt][1],  ah[mt][2],  ah[mt][3],  bl0, bl1);
                mma_bf16(acc[mt][nt], ah[mt][0],  ah[mt][1],  ah[mt][2],  ah[mt][3],  bh0, bh1);
            }
        }
        if (has) {
            int nb = buf ^ 1;
            float av[8] = {aL0.x, aL0.y, aL0.z, aL0.w, aL1.x, aL1.y, aL1.z, aL1.w};
            #pragma unroll
            for (int j = 0; j < 4; j++) {
                __nv_bfloat16 h0, l0, h1, l1;
                split_bf16(av[2 * j], h0, l0);
                split_bf16(av[2 * j + 1], h1, l1);
                Ah[nb][aK / 2 + j][aRow] = packb(h0, h1);
                Al[nb][aK / 2 + j][aRow] = packb(l0, l1);
            }
            float bx[4] = {bL0.x, bL0.y, bL0.z, bL0.w};
            float by[4] = {bL1.x, bL1.y, bL1.z, bL1.w};
            uint32_t bhv[4], blv[4];
            #pragma unroll
            for (int c = 0; c < 4; c++) {
                __nv_bfloat16 h0, l0, h1, l1;
                split_bf16(bx[c], h0, l0);
                split_bf16(by[c], h1, l1);
                bhv[c] = packb(h0, h1);
                blv[c] = packb(l0, l1);
            }
            *(uint4*)&Bh[nb][bKp][bCol] = make_uint4(bhv[0], bhv[1], bhv[2], bhv[3]);
            *(uint4*)&Bl[nb][bKp][bCol] = make_uint4(blv[0], blv[1], blv[2], blv[3]);
            __syncthreads();
            buf = nb;
        }
    }
    // epilogue: c0,c1 -> (row, col 2lk..2lk+1); c2,c3 -> row+8
    #pragma unroll
    for (int mt = 0; mt < 4; mt++) {
        #pragma unroll
        for (int half = 0; half < 2; half++) {
            int r = row0 + wm * 64 + mt * 16 + lm + half * 8;
            #pragma unroll
            for (int nt = 0; nt < 4; nt++) {
                float v0 = acc[mt][nt][half * 2 + 0];
                float v1 = acc[mt][nt][half * 2 + 1];
                size_t off = (size_t)r * N + col0 + wn * 32 + nt * 8 + 2 * lk;
                if (Res) {
                    float2 rv = *(const float2*)(Res + off);
                    v0 += rv.x; v1 += rv.y;
                }
                if (act == 1) { v0 = gelu_f(v0); v1 = gelu_f(v1); }
                *(float2*)(C + off) = make_float2(v0, v1);
            }
        }
    }
}

// batched generic: blockIdx.z selects slice via element strides
__global__ void __launch_bounds__(256)
gemm_bat_kernel(const float* __restrict__ A, size_t sA,
                const float* __restrict__ Bm, size_t sB,
                const float* __restrict__ Res, size_t sR,
                float* __restrict__ C, size_t sC,
                int N, int Kd, int act) {
    size_t z = blockIdx.z;
    gemm_tile_bf16(A + z * sA, Bm + z * sB,
                   Res ? Res + z * sR : nullptr, C + z * sC, N, Kd, act);
}

// QKV fused-batched: blockIdx.z = key*3 + {0:Q,1:K,2:V}
__global__ void __launch_bounds__(256)
gemm_qkv_kernel(const float* __restrict__ x,
                const float* __restrict__ Wq,
                const float* __restrict__ Wk,
                const float* __restrict__ Wv,
                float* __restrict__ q,
                float* __restrict__ k,
                float* __restrict__ v) {
    int z = blockIdx.z;
    int key = z / 3, m = z - key * 3;
    const float* A = x + (size_t)key * BSD;
    const float* B = (m == 0 ? Wq : m == 1 ? Wk : Wv) + (size_t)key * DD * DD;
    float* C = (m == 0 ? q : m == 1 ? k : v) + (size_t)key * BSD;
    gemm_tile_bf16(A, B, nullptr, C, DD, DD, 0);
}

// -------------------- causal MHA, batched over k: grid (BB, HH, KK) ----------
__global__ void attn_kernel(const float* __restrict__ q,
                            const float* __restrict__ k,
                            const float* __restrict__ v,
                            float* __restrict__ o) {
    __shared__ float sq[SS * (DHD + 1)];
    __shared__ float sk[SS * (DHD + 1)];
    __shared__ float sv[SS * (DHD + 1)];
    __shared__ float sp[8 * 64];
    int b = blockIdx.x, h = blockIdx.y;
    size_t kb = (size_t)blockIdx.z * BSD;
    for (int t = threadIdx.x; t < SS * DHD; t += 256) {
        int s = t / DHD, d = t % DHD;
        size_t gi = kb + ((size_t)b * SS + s) * DD + h * DHD + d;
        int si = s * (DHD + 1) + d;
        sq[si] = q[gi]; sk[si] = k[gi]; sv[si] = v[gi];
    }
    __syncthreads();
    int w = threadIdx.x >> 5, lane = threadIdx.x & 31;
    for (int i = w; i < SS; i += 8) {
        float sc[2];
        #pragma unroll
        for (int jj = 0; jj < 2; jj++) {
            int j = lane + jj * 32;
            float val = NEGV;
            if (j < SS && j <= i) {
                float acc = 0.0f;
                #pragma unroll 16
                for (int d = 0; d < DHD; d++)
                    acc += sq[i * (DHD + 1) + d] * sk[j * (DHD + 1) + d];
                val = acc * SCL;
            }
            sc[jj] = val;
        }
        float m = warp_max(fmaxf(sc[0], sc[1]));
        float e0 = expf(sc[0] - m), e1 = expf(sc[1] - m);
        if (lane + 32 >= SS) e1 = 0.0f;
        float s = warp_sum(e0 + e1);
        float inv = 1.0f / s;
        sp[w * 64 + lane] = e0 * inv;
        if (lane + 32 < 64) sp[w * 64 + 32 + lane] = e1 * inv;
        __syncwarp();
        #pragma unroll
        for (int dd = 0; dd < 2; dd++) {
            int d = lane + dd * 32;
            float acc = 0.0f;
            #pragma unroll 10
            for (int j = 0; j < SS; j++)
                acc += sp[w * 64 + j] * sv[j * (DHD + 1) + d];
            o[kb + ((size_t)b * SS + i) * DD + h * DHD + d] = acc;
        }
    }
}

// -------------------- h_seq = mean_k emb[k][ids[k]] --------------------------
__global__ void hseq_kernel(const float* __restrict__ emb,
                            const int* __restrict__ ids,
                            float* __restrict__ hseq) {
    int bs = blockIdx.x, d = threadIdx.x;
    float acc = 0.0f;
    #pragma unroll
    for (int kk = 0; kk < KK; kk++) {
        int id = ids[(size_t)kk * BS + bs];
        acc += emb[(size_t)kk * VV * DD + (size_t)id * DD + d];
    }
    hseq[(size_t)bs * DD + d] = acc * 0.25f;
}

// -------------------- noisy top-2 gating + combine ---------------------------
__global__ void gate_kernel(const float* __restrict__ hseq,
                            const float* __restrict__ Wg,
                            const float* __restrict__ Wn,
                            const float* __restrict__ eps,
                            const float* __restrict__ hk,
                            float* __restrict__ out) {
    __shared__ float red[8 * 256];
    __shared__ float sg[KK];
    int bs = blockIdx.x, d = threadIdx.x;
    float hx = hseq[(size_t)bs * DD + d];
    #pragma unroll
    for (int kk = 0; kk < KK; kk++) {
        red[kk * 256 + d]       = hx * Wg[d * KK + kk];
        red[(4 + kk) * 256 + d] = hx * Wn[d * KK + kk];
    }
    __syncthreads();
    for (int st = 128; st > 0; st >>= 1) {
        if (d < st) {
            #pragma unroll
            for (int j = 0; j < 8; j++)
                red[j * 256 + d] += red[j * 256 + d + st];
        }
        __syncthreads();
    }
    if (d == 0) {
        float lg[KK];
        #pragma unroll
        for (int kk = 0; kk < KK; kk++) {
            float noise = red[(4 + kk) * 256];
            float sp = (noise > 0.0f) ? (noise + log1pf(expf(-noise)))
                                      : log1pf(expf(noise));
            lg[kk] = red[kk * 256] + sp * eps[(size_t)bs * KK + kk];
        }
        int i1 = 0; float v1 = lg[0];
        #pragma unroll
        for (int kk = 1; kk < KK; kk++) if (lg[kk] > v1) { v1 = lg[kk]; i1 = kk; }
        int i2 = -1; float v2 = -INFINITY;
        #pragma unroll
        for (int kk = 0; kk < KK; kk++)
            if (kk != i1 && lg[kk] > v2) { v2 = lg[kk]; i2 = kk; }
        float e2 = expf(v2 - v1);
        float den = 1.0f / (1.0f + e2);
        #pragma unroll
        for (int kk = 0; kk < KK; kk++) sg[kk] = 0.0f;
        sg[i1] = den;
        sg[i2] = e2 * den;
    }
    __syncthreads();
    float acc = 0.0f;
    #pragma unroll
    for (int kk = 0; kk < KK; kk++)
        acc += sg[kk] * hk[(size_t)kk * BSD + (size_t)bs * DD + d];
    out[(size_t)bs * DD + d] = acc;
}

// -------------------- launch -------------------------------------------------
extern "C" void kernel_launch(void* const* d_in, const int* in_sizes, int n_in,
                              void* d_out, int out_size) {
    const int*   ids   = (const int*)d_in[0];
    const int*   items = (const int*)d_in[1];
    const int*   adj   = (const int*)d_in[2];
    const int*   alias = (const int*)d_in[3];
    const float* eps   = (const float*)d_in[4];
    const float* emb   = (const float*)d_in[5];
    const float* agg_a = (const float*)d_in[6];
    const float* Wq    = (const float*)d_in[7];
    const float* Wk    = (const float*)d_in[8];
    const float* Wv    = (const float*)d_in[9];
    const float* Wo    = (const float*)d_in[10];
    const float* ln1g  = (const float*)d_in[11];
    const float* ln1b  = (const float*)d_in[12];
    const float* W1    = (const float*)d_in[13];
    const float* W2    = (const float*)d_in[14];
    const float* ln2g  = (const float*)d_in[15];
    const float* ln2b  = (const float*)d_in[16];
    const float* Wg    = (const float*)d_in[17];
    const float* Wn    = (const float*)d_in[18];
    float* out = (float*)d_out;

    float *p_hloc, *p_h, *p_x, *p_q, *p_k, *p_v, *p_o, *p_ff, *p_hseq;
    cudaGetSymbolAddress((void**)&p_hloc, g_hloc);
    cudaGetSymbolAddress((void**)&p_h,    g_h);
    cudaGetSymbolAddress((void**)&p_x,    g_x);
    cudaGetSymbolAddress((void**)&p_q,    g_q);
    cudaGetSymbolAddress((void**)&p_k,    g_k);
    cudaGetSymbolAddress((void**)&p_v,    g_v);
    cudaGetSymbolAddress((void**)&p_o,    g_o);
    cudaGetSymbolAddress((void**)&p_ff,   g_ff);
    cudaGetSymbolAddress((void**)&p_hseq, g_hseq);

    const int smem_agg = (SS * DD + 4 * DD + SS * SS) * sizeof(float);  // 65296
    cudaFuncSetAttribute(localagg_kernel,
                         cudaFuncAttributeMaxDynamicSharedMemorySize, smem_agg);

    const size_t sW = (size_t)DD * DD;
    const size_t sFF = (size_t)BS * FFD;

    hseq_kernel<<<BS, 256>>>(emb, ids, p_hseq);

    // graph aggregation + alias + LN1, all keys at once
    localagg_kernel<<<dim3(BB, KK), 256, smem_agg>>>(emb, items, adj, agg_a, p_hloc);
    ln_bat_kernel<<<dim3(BS, KK), 256>>>(p_hloc, alias, ln1g, ln1b, p_h, p_x);

    // QKV for all keys (12 GEMMs in one launch)
    gemm_qkv_kernel<<<dim3(DD / TBN, BS / TBM, KK * 3), 256>>>(
        p_x, Wq, Wk, Wv, p_q, p_k, p_v);

    attn_kernel<<<dim3(BB, HH, KK), 256>>>(p_q, p_k, p_v, p_o);

    // h += O @ Wo   (all keys)
    gemm_bat_kernel<<<dim3(DD / TBN, BS / TBM, KK), 256>>>(
        p_o, (size_t)BSD, Wo, sW, p_h, (size_t)BSD, p_h, (size_t)BSD, DD, DD, 0);

    // LN2 (all keys)
    ln_bat_kernel<<<dim3(BS, KK), 256>>>(p_h, nullptr, ln2g, ln2b, nullptr, p_x);

    // FFN1: gelu(x @ W1)  (all keys)
    gemm_bat_kernel<<<dim3(FFD / TBN, BS / TBM, KK), 256>>>(
        p_x, (size_t)BSD, W1, (size_t)DD * FFD, nullptr, 0, p_ff, sFF, FFD, DD, 1);

    // FFN2: h += ff @ W2  (all keys)
    gemm_bat_kernel<<<dim3(DD / TBN, BS / TBM, KK), 256>>>(
        p_ff, sFF, W2, (size_t)FFD * DD, p_h, (size_t)BSD, p_h, (size_t)BSD, DD, FFD, 0);

    gate_kernel<<<BS, 256>>>(p_hseq, Wg, Wn, eps, p_h, out);
}